// round 15
// baseline (speedup 1.0000x reference)
#include <cuda_runtime.h>
#include <math.h>

#define Dd 768
#define Mq 8
#define Bb 16
#define Ss 2048
#define SPLITS 16
#define CHUNK 128
#define KC 48
#define NS_A 48     /* 2304 / KC */
#define NS_B 144    /* 6912 / KC */
#define NS_2 16     /* 768 / KC  */

#define INV_SQRT_D 0.036084391824351615f

// ---------------- scratch (device globals; no allocation) ----------------
__device__ float    g_qs  [Mq][Dd];            // q * ln_scale
__device__ float    g_QS  [Mq];                // sum_d q*scale
__device__ float    g_QB  [Mq];                // (sum_d q*bias) / sqrt(D)
__device__ float    g_xa  [Bb][3*Dd];          // pooled_trad (mean atomic / max,min decoded)
__device__ float    g_xb  [Bb][(Mq+1)*Dd];     // pooled_learn (merged atomic accum + clf)
__device__ unsigned g_imax[Bb][Dd];            // ordered-uint max accum
__device__ unsigned g_imin[Bb][Dd];            // ordered-uint min accum
__device__ float    g_den [Bb][Mq];            // softmax denominators (atomic)
__device__ float    g_hA  [Bb*Dd];             // MLP hidden branch A (atomic accum)
__device__ float    g_hB  [Bb*Dd];             // MLP hidden branch B (atomic accum)

// monotone float <-> unsigned order transform (for atomicMax/Min on floats)
__device__ __forceinline__ unsigned ford(float f) {
    unsigned u = __float_as_uint(f);
    return (u & 0x80000000u) ? ~u : (u | 0x80000000u);
}
__device__ __forceinline__ float funord(unsigned u) {
    return __uint_as_float((u & 0x80000000u) ? (u & 0x7fffffffu) : ~u);
}

// lengths >= 1 always; detect int32 vs int64 storage.
__device__ __forceinline__ int read_len(const int* p32, int b) {
    return (p32[1] == 0) ? p32[2 * b] : p32[b];
}

__device__ __forceinline__ float wredsum(float v) {
    v += __shfl_down_sync(0xffffffffu, v, 16);
    v += __shfl_down_sync(0xffffffffu, v, 8);
    v += __shfl_down_sync(0xffffffffu, v, 4);
    v += __shfl_down_sync(0xffffffffu, v, 2);
    v += __shfl_down_sync(0xffffffffu, v, 1);
    return v;
}
__device__ __forceinline__ float bflysum(float v) {
    v += __shfl_xor_sync(0xffffffffu, v, 16);
    v += __shfl_xor_sync(0xffffffffu, v, 8);
    v += __shfl_xor_sync(0xffffffffu, v, 4);
    v += __shfl_xor_sync(0xffffffffu, v, 2);
    v += __shfl_xor_sync(0xffffffffu, v, 1);
    return v;
}

// ---------------- kernel 0a: precompute qs = q*scale, QS, QB ----------------
__global__ __launch_bounds__(256) void k_prep(
    const float* __restrict__ q, const float* __restrict__ lns, const float* __restrict__ lnb)
{
    const int lane = threadIdx.x & 31;
    const int m    = threadIdx.x >> 5;
    float sQS = 0.f, sQB = 0.f;
    #pragma unroll
    for (int i = 0; i < 6; i++) {
        int d = lane * 4 + i * 128;
        float4 qv = *(const float4*)(q + m * Dd + d);
        float4 sv = *(const float4*)(lns + d);
        float4 bv = *(const float4*)(lnb + d);
        float4 qs = make_float4(qv.x*sv.x, qv.y*sv.y, qv.z*sv.z, qv.w*sv.w);
        *(float4*)&g_qs[m][d] = qs;
        sQS += qs.x + qs.y + qs.z + qs.w;
        sQB += qv.x*bv.x + qv.y*bv.y + qv.z*bv.z + qv.w*bv.w;
    }
    sQS = wredsum(sQS);
    sQB = wredsum(sQB);
    if (lane == 0) { g_QS[m] = sQS; g_QB[m] = sQB * INV_SQRT_D; }
}

// ---------------- kernel 0b: init accumulators, out = bias, clf copy ----------------
__global__ __launch_bounds__(256) void k_init(
    const float* __restrict__ tokens,
    const float* __restrict__ b2a, const float* __restrict__ b2b, float* __restrict__ out)
{
    const int idx = blockIdx.x * 256 + threadIdx.x;   // 0..98303
    // zero merged accumulation region of g_xb
    (&g_xb[0][0])[ (idx / ((Mq + 1) * Dd)) * ((Mq + 1) * Dd) ] = (&g_xb[0][0])[0]; // no-op placeholder avoided below
    // Correct approach: idx indexes [Bb][Mq*Dd]
    {
        const int b = idx / (Mq * Dd);
        const int r = idx - b * (Mq * Dd);
        g_xb[b][r] = 0.f;
    }
    if (idx < Bb * Dd) {
        const int b = idx / Dd;
        const int j = idx - b * Dd;
        g_hA[idx] = 0.f;
        g_hB[idx] = 0.f;
        g_xa[b][j] = 0.f;                 // mean accumulator
        g_imax[b][j] = 0u;                // below ord(-inf)
        g_imin[b][j] = 0xffffffffu;       // above ord(+inf)
        g_xb[b][Mq*Dd + j] = tokens[(size_t)b * (Ss + 1) * Dd + j];  // clf token
    }
    if (idx < Bb * 2 * Dd) {
        const int rem = idx % (2 * Dd);
        const int br  = rem / Dd;
        const int j   = rem - br * Dd;
        out[idx] = br ? b2b[j] : b2a[j];
    }
    if (idx < Bb * Mq) g_den[idx / Mq][idx % Mq] = 0.f;
}

// ---------------- scores for 4 tokens per warp (quarter h of 16) ----------------
template<bool FULL>
__device__ __forceinline__ void score_half(
    const float* __restrict__ xbase, int cnt, int lane, int w, int h, float* __restrict__ sh_sc)
{
    float acc[4][Mq];
    float ps[4], pq[4];
    #pragma unroll
    for (int k = 0; k < 4; k++) {
        ps[k] = 0.f; pq[k] = 0.f;
        #pragma unroll
        for (int m = 0; m < Mq; m++) acc[k][m] = 0.f;
    }

    #pragma unroll
    for (int j = 0; j < 6; j++) {
        const int dj = lane * 4 + j * 128;
        float4 qs[Mq];
        #pragma unroll
        for (int m = 0; m < Mq; m++) qs[m] = *(const float4*)&g_qs[m][dj];

        #pragma unroll
        for (int k = 0; k < 4; k++) {
            const int sl = w + 8 * (4 * h + k);
            if (FULL || sl < cnt) {
                float4 x = *(const float4*)(xbase + (size_t)sl * Dd + dj);
                ps[k] += x.x + x.y + x.z + x.w;
                pq[k] = fmaf(x.x, x.x, fmaf(x.y, x.y, fmaf(x.z, x.z, fmaf(x.w, x.w, pq[k]))));
                #pragma unroll
                for (int m = 0; m < Mq; m++) {
                    acc[k][m] = fmaf(qs[m].x, x.x, fmaf(qs[m].y, x.y,
                                fmaf(qs[m].z, x.z, fmaf(qs[m].w, x.w, acc[k][m]))));
                }
            }
        }
    }

    #pragma unroll
    for (int k = 0; k < 4; k++) {
        const int sl = w + 8 * (4 * h + k);
        if (FULL || sl < cnt) {
            float ts = wredsum(ps[k]);
            float tq = wredsum(pq[k]);
            float td[Mq];
            #pragma unroll
            for (int m = 0; m < Mq; m++) td[m] = wredsum(acc[k][m]);
            if (lane == 0) {
                float mu  = ts * (1.f / Dd);
                float var = fmaf(-mu, mu, tq * (1.f / Dd));
                float r   = rsqrtf(var + 1e-5f) * INV_SQRT_D;
                #pragma unroll
                for (int m = 0; m < Mq; m++)
                    sh_sc[sl * 9 + m] = fmaf(r, fmaf(-mu, g_QS[m], td[m]), g_QB[m]);
            }
        } else if (lane == 0) {
            #pragma unroll
            for (int m = 0; m < Mq; m++) sh_sc[sl * 9 + m] = -INFINITY;
        }
    }
}

// ---------------- kernel 1: merged scores + softmax + pooling/merge (atomic out) --------
__global__ __launch_bounds__(256) void k_main(
    const float* __restrict__ tokens, const int* __restrict__ lengths)
{
    const int bs = blockIdx.x;
    const int b  = bs >> 4;
    const int sp = bs & (SPLITS - 1);
    const int len  = read_len(lengths, b);
    const int s0   = sp * CHUNK;
    const int cnt0 = min(s0 + CHUNK, len) - s0;
    if (cnt0 <= 0) return;
    const int cnt = cnt0;

    __shared__ float sh_sc[CHUNK * 9];
    __shared__ float sh_w [CHUNK * Mq];

    const int t    = threadIdx.x;
    const int lane = t & 31;
    const int w    = t >> 5;

    const float* xbase = tokens + ((size_t)(b * (Ss + 1) + 1 + s0)) * Dd;

    // phase 1: scores (warp-per-token, four quarter-batches to bound registers)
    if (cnt == CHUNK) {
        score_half<true >(xbase, cnt, lane, w, 0, sh_sc);
        score_half<true >(xbase, cnt, lane, w, 1, sh_sc);
        score_half<true >(xbase, cnt, lane, w, 2, sh_sc);
        score_half<true >(xbase, cnt, lane, w, 3, sh_sc);
    } else {
        score_half<false>(xbase, cnt, lane, w, 0, sh_sc);
        score_half<false>(xbase, cnt, lane, w, 1, sh_sc);
        score_half<false>(xbase, cnt, lane, w, 2, sh_sc);
        score_half<false>(xbase, cnt, lane, w, 3, sh_sc);
    }
    __syncthreads();

    // phase 2: weights w = exp(score) — scores are O(0.02), no max-subtraction needed.
    // Mathematically identical to softmax (den accumulated globally, divided in k_norm).
    {
        float sc[4], e[4];
        #pragma unroll
        for (int i = 0; i < 4; i++) sc[i] = sh_sc[(lane + 32 * i) * 9 + w];
        float es = 0.f;
        #pragma unroll
        for (int i = 0; i < 4; i++) {
            e[i] = (sc[i] == -INFINITY) ? 0.f : __expf(sc[i]);
            es += e[i];
        }
        float den = bflysum(es);
        #pragma unroll
        for (int i = 0; i < 4; i++) sh_w[(lane + 32 * i) * Mq + w] = e[i];
        if (lane == 0) atomicAdd(&g_den[b][w], den);
    }
    __syncthreads();

    // phase 3: pooling + weighted merge; atomic accumulation into global buffers
    if (t < Dd / 4) {
        const int d0 = t * 4;
        float4 s4  = make_float4(0.f, 0.f, 0.f, 0.f);
        float4 mx4 = make_float4(-INFINITY, -INFINITY, -INFINITY, -INFINITY);
        float4 mn4 = make_float4( INFINITY,  INFINITY,  INFINITY,  INFINITY);
        float4 mg[Mq];
        #pragma unroll
        for (int m = 0; m < Mq; m++) mg[m] = make_float4(0.f, 0.f, 0.f, 0.f);

        #pragma unroll 8
        for (int s = 0; s < cnt; s++) {
            float4 x  = *(const float4*)(xbase + (size_t)s * Dd + d0);
            float4 w0 = *(const float4*)&sh_w[s * Mq];
            float4 w1 = *(const float4*)&sh_w[s * Mq + 4];
            s4.x += x.x; s4.y += x.y; s4.z += x.z; s4.w += x.w;
            mx4.x = fmaxf(mx4.x, x.x); mx4.y = fmaxf(mx4.y, x.y);
            mx4.z = fmaxf(mx4.z, x.z); mx4.w = fmaxf(mx4.w, x.w);
            mn4.x = fminf(mn4.x, x.x); mn4.y = fminf(mn4.y, x.y);
            mn4.z = fminf(mn4.z, x.z); mn4.w = fminf(mn4.w, x.w);
            float wm[Mq] = {w0.x, w0.y, w0.z, w0.w, w1.x, w1.y, w1.z, w1.w};
            #pragma unroll
            for (int m = 0; m < Mq; m++) {
                mg[m].x = fmaf(wm[m], x.x, mg[m].x);
                mg[m].y = fmaf(wm[m], x.y, mg[m].y);
                mg[m].z = fmaf(wm[m], x.z, mg[m].z);
                mg[m].w = fmaf(wm[m], x.w, mg[m].w);
            }
        }
        // mean accumulation
        atomicAdd(&g_xa[b][d0 + 0], s4.x);
        atomicAdd(&g_xa[b][d0 + 1], s4.y);
        atomicAdd(&g_xa[b][d0 + 2], s4.z);
        atomicAdd(&g_xa[b][d0 + 3], s4.w);
        // max/min via ordered-uint transform
        atomicMax(&g_imax[b][d0 + 0], ford(mx4.x));
        atomicMax(&g_imax[b][d0 + 1], ford(mx4.y));
        atomicMax(&g_imax[b][d0 + 2], ford(mx4.z));
        atomicMax(&g_imax[b][d0 + 3], ford(mx4.w));
        atomicMin(&g_imin[b][d0 + 0], ford(mn4.x));
        atomicMin(&g_imin[b][d0 + 1], ford(mn4.y));
        atomicMin(&g_imin[b][d0 + 2], ford(mn4.z));
        atomicMin(&g_imin[b][d0 + 3], ford(mn4.w));
        // merged accumulation
        #pragma unroll
        for (int m = 0; m < Mq; m++) {
            float* dst = &g_xb[b][m * Dd + d0];
            atomicAdd(dst + 0, mg[m].x);
            atomicAdd(dst + 1, mg[m].y);
            atomicAdd(dst + 2, mg[m].z);
            atomicAdd(dst + 3, mg[m].w);
        }
    }
}

// ---------------- kernel 2: normalize (divide by den / len, decode max/min) ----------
__global__ __launch_bounds__(256) void k_norm(const int* __restrict__ lengths)
{
    const int idx = blockIdx.x * 256 + threadIdx.x;   // 0..98303 = Bb*Mq*Dd
    const int b = idx / (Mq * Dd);
    const int r = idx - b * (Mq * Dd);
    const int m = r / Dd;
    const int j = r - m * Dd;
    float den = g_den[b][m];
    g_xb[b][m * Dd + j] *= (den > 0.f) ? (1.f / den) : 0.f;
    if (m == 0) {
        g_xa[b][j] *= 1.f / (float)read_len(lengths, b);
        g_xa[b][Dd + j]     = funord(g_imax[b][j]);
        g_xa[b][2 * Dd + j] = funord(g_imin[b][j]);
    }
}

// ---------------- GEMM body (all 16 batch rows per CTA; W read once) ----------------
__device__ __forceinline__ void gemm_body16_atomic(
    const float* __restrict__ A, int lda, const float* __restrict__ W,
    float* __restrict__ H, int hstride, int hoff, int k0)
{
    __shared__ float sA[16 * KC];
    const int j = blockIdx.x * 256 + threadIdx.x;   // blockIdx.x in 0..2

    for (int i = threadIdx.x; i < 16 * KC; i += 256) {
        int bb = i / KC;
        int kk = i - bb * KC;
        sA[i] = A[bb * lda + k0 + kk];
    }
    __syncthreads();

    float acc[16];
    #pragma unroll
    for (int bb = 0; bb < 16; bb++) acc[bb] = 0.f;

    const float* Wp = W + (size_t)k0 * Dd + j;
    #pragma unroll
    for (int kk = 0; kk < KC; kk += 8) {
        float wv[8];
        #pragma unroll
        for (int u = 0; u < 8; u++) wv[u] = Wp[u * Dd];
        Wp += 8 * Dd;
        #pragma unroll
        for (int bb = 0; bb < 16; bb++) {
            float4 a0 = *(const float4*)&sA[bb * KC + kk];
            float4 a1 = *(const float4*)&sA[bb * KC + kk + 4];
            float v = acc[bb];
            v = fmaf(a0.x, wv[0], v);
            v = fmaf(a0.y, wv[1], v);
            v = fmaf(a0.z, wv[2], v);
            v = fmaf(a0.w, wv[3], v);
            v = fmaf(a1.x, wv[4], v);
            v = fmaf(a1.y, wv[5], v);
            v = fmaf(a1.z, wv[6], v);
            v = fmaf(a1.w, wv[7], v);
            acc[bb] = v;
        }
    }
    #pragma unroll
    for (int bb = 0; bb < 16; bb++)
        atomicAdd(&H[(size_t)bb * hstride + hoff + j], acc[bb]);
}

// layer-1 GEMM, both branches, atomic into g_h
__global__ __launch_bounds__(256) void k_g1(const float* __restrict__ w1a, const float* __restrict__ w1b)
{
    const int br = blockIdx.z;
    if (br == 0 && blockIdx.y >= NS_A) return;
    const float* A = br ? &g_xb[0][0] : &g_xa[0][0];
    const int lda  = br ? (Mq + 1) * Dd : 3 * Dd;
    const float* W = br ? w1b : w1a;
    float* H = br ? g_hB : g_hA;
    gemm_body16_atomic(A, lda, W, H, Dd, 0, blockIdx.y * KC);
}

// activation: h = gelu(h + b1), both branches
__global__ __launch_bounds__(256) void k_act(const float* __restrict__ b1a, const float* __restrict__ b1b)
{
    const int br  = blockIdx.y;
    const int idx = blockIdx.x * 256 + threadIdx.x;   // 0..12287
    const int j   = idx % Dd;
    float* H = br ? g_hB : g_hA;
    float v = H[idx] + (br ? b1b[j] : b1a[j]);
    H[idx] = 0.5f * v * (1.f + erff(v * 0.70710678118654752f));
}

// layer-2 GEMM, both branches, atomic into out (pre-initialized with bias)
__global__ __launch_bounds__(256) void k_g2(const float* __restrict__ w2a, const float* __restrict__ w2b,
                                            float* __restrict__ out)
{
    const int br = blockIdx.z;
    const float* A = br ? g_hB : g_hA;
    const float* W = br ? w2b : w2a;
    gemm_body16_atomic(A, Dd, W, out, 2 * Dd, br * Dd, blockIdx.y * KC);
}

// ---------------- launch ----------------
extern "C" void kernel_launch(void* const* d_in, const int* in_sizes, int n_in,
                              void* d_out, int out_size)
{
    const float* tokens  = (const float*)d_in[0];
    const int*   lengths = (const int*)d_in[1];
    const float* q       = (const float*)d_in[2];
    const float* lns     = (const float*)d_in[3];
    const float* lnb     = (const float*)d_in[4];
    const float* w1a     = (const float*)d_in[5];
    const float* b1a     = (const float*)d_in[6];
    const float* w2a     = (const float*)d_in[7];
    const float* b2a     = (const float*)d_in[8];
    const float* w1b     = (const float*)d_in[9];
    const float* b1b     = (const float*)d_in[10];
    const float* w2b     = (const float*)d_in[11];
    const float* b2b     = (const float*)d_in[12];
    float* out = (float*)d_out;

    k_prep<<<1, 256>>>(q, lns, lnb);
    k_init<<<384, 256>>>(tokens, b2a, b2b, out);
    k_main<<<Bb * SPLITS, 256>>>(tokens, lengths);
    k_norm<<<384, 256>>>(lengths);

    k_g1<<<dim3(3, NS_B, 2), 256>>>(w1a, w1b);
    k_act<<<dim3(48, 2), 256>>>(b1a, b1b);
    k_g2<<<dim3(3, NS_2, 2), 256>>>(w2a, w2b, out);
}

// round 16
// speedup vs baseline: 1.1943x; 1.1943x over previous
#include <cuda_runtime.h>
#include <math.h>

#define Dd 768
#define Mq 8
#define Bb 16
#define Ss 2048
#define SPLITS 16
#define CHUNK 128
#define KC 48
#define NS_A 48     /* 2304 / KC */
#define NS_B 144    /* 6912 / KC */
#define NS_2 16     /* 768 / KC  */

#define INV_SQRT_D 0.036084391824351615f

// ---------------- scratch (device globals; no allocation) ----------------
__device__ float g_qs  [Mq][Dd];               // q * ln_scale
__device__ float g_QS  [Mq];                   // sum_d q*scale
__device__ float g_QB  [Mq];                   // (sum_d q*bias) / sqrt(D)
__device__ float g_pm  [Bb][SPLITS][Mq][Dd];   // partial merged (unnormalized)
__device__ float g_psum[Bb][SPLITS][Dd];
__device__ float g_pmax[Bb][SPLITS][Dd];
__device__ float g_pmin[Bb][SPLITS][Dd];
__device__ float g_smax[Bb][SPLITS][Mq];
__device__ float g_sden[Bb][SPLITS][Mq];
__device__ int   g_cnt [Bb][SPLITS];
__device__ float g_xa  [Bb][3*Dd];             // pooled_trad
__device__ float g_xb  [Bb][(Mq+1)*Dd];        // pooled_learn
__device__ float g_hA  [Bb*Dd];                // MLP hidden branch A (atomic accum)
__device__ float g_hB  [Bb*Dd];                // MLP hidden branch B (atomic accum)

// lengths >= 1 always; detect int32 vs int64 storage.
__device__ __forceinline__ int read_len(const int* p32, int b) {
    return (p32[1] == 0) ? p32[2 * b] : p32[b];
}

__device__ __forceinline__ float wredsum(float v) {
    v += __shfl_down_sync(0xffffffffu, v, 16);
    v += __shfl_down_sync(0xffffffffu, v, 8);
    v += __shfl_down_sync(0xffffffffu, v, 4);
    v += __shfl_down_sync(0xffffffffu, v, 2);
    v += __shfl_down_sync(0xffffffffu, v, 1);
    return v;
}
__device__ __forceinline__ float bflysum(float v) {
    v += __shfl_xor_sync(0xffffffffu, v, 16);
    v += __shfl_xor_sync(0xffffffffu, v, 8);
    v += __shfl_xor_sync(0xffffffffu, v, 4);
    v += __shfl_xor_sync(0xffffffffu, v, 2);
    v += __shfl_xor_sync(0xffffffffu, v, 1);
    return v;
}
__device__ __forceinline__ float bflymax(float v) {
    v = fmaxf(v, __shfl_xor_sync(0xffffffffu, v, 16));
    v = fmaxf(v, __shfl_xor_sync(0xffffffffu, v, 8));
    v = fmaxf(v, __shfl_xor_sync(0xffffffffu, v, 4));
    v = fmaxf(v, __shfl_xor_sync(0xffffffffu, v, 2));
    v = fmaxf(v, __shfl_xor_sync(0xffffffffu, v, 1));
    return v;
}
// reductions over the low 16 lanes
__device__ __forceinline__ float bflysum16(float v) {
    v += __shfl_xor_sync(0xffffu, v, 8);
    v += __shfl_xor_sync(0xffffu, v, 4);
    v += __shfl_xor_sync(0xffffu, v, 2);
    v += __shfl_xor_sync(0xffffu, v, 1);
    return v;
}
__device__ __forceinline__ float bflymax16(float v) {
    v = fmaxf(v, __shfl_xor_sync(0xffffu, v, 8));
    v = fmaxf(v, __shfl_xor_sync(0xffffu, v, 4));
    v = fmaxf(v, __shfl_xor_sync(0xffffu, v, 2));
    v = fmaxf(v, __shfl_xor_sync(0xffffu, v, 1));
    return v;
}

// ---------------- kernel 0a: precompute qs = q*scale, QS, QB ----------------
__global__ __launch_bounds__(256) void k_prep(
    const float* __restrict__ q, const float* __restrict__ lns, const float* __restrict__ lnb)
{
    const int lane = threadIdx.x & 31;
    const int m    = threadIdx.x >> 5;
    float sQS = 0.f, sQB = 0.f;
    #pragma unroll
    for (int i = 0; i < 6; i++) {
        int d = lane * 4 + i * 128;
        float4 qv = *(const float4*)(q + m * Dd + d);
        float4 sv = *(const float4*)(lns + d);
        float4 bv = *(const float4*)(lnb + d);
        float4 qs = make_float4(qv.x*sv.x, qv.y*sv.y, qv.z*sv.z, qv.w*sv.w);
        *(float4*)&g_qs[m][d] = qs;
        sQS += qs.x + qs.y + qs.z + qs.w;
        sQB += qv.x*bv.x + qv.y*bv.y + qv.z*bv.z + qv.w*bv.w;
    }
    sQS = wredsum(sQS);
    sQB = wredsum(sQB);
    if (lane == 0) { g_QS[m] = sQS; g_QB[m] = sQB * INV_SQRT_D; }
}

// ---------------- kernel 0b: zero hidden accumulators, out = bias ----------------
__global__ __launch_bounds__(256) void k_init(
    const float* __restrict__ b2a, const float* __restrict__ b2b, float* __restrict__ out)
{
    const int idx = blockIdx.x * 256 + threadIdx.x;   // 0..24575
    if (idx < Bb * Dd) { g_hA[idx] = 0.f; g_hB[idx] = 0.f; }
    const int rem = idx % (2 * Dd);
    const int br  = rem / Dd;
    const int j   = rem - br * Dd;
    out[idx] = br ? b2b[j] : b2a[j];
}

// ---------------- scores for 2 tokens per warp, all loads hoisted (MLP=12) ----------
template<bool FULL>
__device__ __forceinline__ void score_pair(
    const float* __restrict__ xbase, int cnt, int lane, int w, int p, float* __restrict__ sh_sc)
{
    const int slA = w + 8 * (2 * p);
    const int slB = w + 8 * (2 * p + 1);
    const bool vA = FULL || (slA < cnt);
    const bool vB = FULL || (slB < cnt);

    // hoist all 12 row loads before any compute (front-batched MLP)
    float4 x0[6], x1[6];
    #pragma unroll
    for (int j = 0; j < 6; j++) {
        const int dj = lane * 4 + j * 128;
        x0[j] = vA ? *(const float4*)(xbase + (size_t)slA * Dd + dj)
                   : make_float4(0.f, 0.f, 0.f, 0.f);
        x1[j] = vB ? *(const float4*)(xbase + (size_t)slB * Dd + dj)
                   : make_float4(0.f, 0.f, 0.f, 0.f);
    }

    float acc0[Mq], acc1[Mq];
    float ps0 = 0.f, ps1 = 0.f, pq0 = 0.f, pq1 = 0.f;
    #pragma unroll
    for (int m = 0; m < Mq; m++) { acc0[m] = 0.f; acc1[m] = 0.f; }

    #pragma unroll
    for (int j = 0; j < 6; j++) {
        const int dj = lane * 4 + j * 128;
        float4 a = x0[j], bq = x1[j];
        ps0 += a.x + a.y + a.z + a.w;
        ps1 += bq.x + bq.y + bq.z + bq.w;
        pq0 = fmaf(a.x, a.x, fmaf(a.y, a.y, fmaf(a.z, a.z, fmaf(a.w, a.w, pq0))));
        pq1 = fmaf(bq.x, bq.x, fmaf(bq.y, bq.y, fmaf(bq.z, bq.z, fmaf(bq.w, bq.w, pq1))));
        #pragma unroll
        for (int m = 0; m < Mq; m++) {
            float4 qv = *(const float4*)&g_qs[m][dj];   // L1/L2-hot, shared by both tokens
            acc0[m] = fmaf(qv.x, a.x,  fmaf(qv.y, a.y,  fmaf(qv.z, a.z,  fmaf(qv.w, a.w,  acc0[m]))));
            acc1[m] = fmaf(qv.x, bq.x, fmaf(qv.y, bq.y, fmaf(qv.z, bq.z, fmaf(qv.w, bq.w, acc1[m]))));
        }
    }

    // token A reduction
    {
        float ts = wredsum(ps0);
        float tq = wredsum(pq0);
        float td[Mq];
        #pragma unroll
        for (int m = 0; m < Mq; m++) td[m] = wredsum(acc0[m]);
        if (lane == 0) {
            if (vA) {
                float mu  = ts * (1.f / Dd);
                float var = fmaf(-mu, mu, tq * (1.f / Dd));
                float r   = rsqrtf(var + 1e-5f) * INV_SQRT_D;
                #pragma unroll
                for (int m = 0; m < Mq; m++)
                    sh_sc[slA * 9 + m] = fmaf(r, fmaf(-mu, g_QS[m], td[m]), g_QB[m]);
            } else {
                #pragma unroll
                for (int m = 0; m < Mq; m++) sh_sc[slA * 9 + m] = -INFINITY;
            }
        }
    }
    // token B reduction
    {
        float ts = wredsum(ps1);
        float tq = wredsum(pq1);
        float td[Mq];
        #pragma unroll
        for (int m = 0; m < Mq; m++) td[m] = wredsum(acc1[m]);
        if (lane == 0) {
            if (vB) {
                float mu  = ts * (1.f / Dd);
                float var = fmaf(-mu, mu, tq * (1.f / Dd));
                float r   = rsqrtf(var + 1e-5f) * INV_SQRT_D;
                #pragma unroll
                for (int m = 0; m < Mq; m++)
                    sh_sc[slB * 9 + m] = fmaf(r, fmaf(-mu, g_QS[m], td[m]), g_QB[m]);
            } else {
                #pragma unroll
                for (int m = 0; m < Mq; m++) sh_sc[slB * 9 + m] = -INFINITY;
            }
        }
    }
}

// ---------------- kernel 1: merged scores + softmax + pooling/merge ----------------
__global__ __launch_bounds__(256) void k_main(
    const float* __restrict__ tokens, const int* __restrict__ lengths)
{
    const int bs = blockIdx.x;
    const int b  = bs >> 4;
    const int sp = bs & (SPLITS - 1);
    const int len  = read_len(lengths, b);
    const int s0   = sp * CHUNK;
    const int cnt0 = min(s0 + CHUNK, len) - s0;
    if (threadIdx.x == 0) g_cnt[b][sp] = cnt0 > 0 ? cnt0 : 0;
    if (cnt0 <= 0) return;
    const int cnt = cnt0;

    __shared__ float sh_sc[CHUNK * 9];
    __shared__ float sh_w [CHUNK * Mq];

    const int t    = threadIdx.x;
    const int lane = t & 31;
    const int w    = t >> 5;

    const float* xbase = tokens + ((size_t)(b * (Ss + 1) + 1 + s0)) * Dd;

    // phase 1: scores (warp handles 16 tokens as 8 prefetched pairs)
    if (cnt == CHUNK) {
        for (int p = 0; p < 8; p++) score_pair<true >(xbase, cnt, lane, w, p, sh_sc);
    } else {
        for (int p = 0; p < 8; p++) score_pair<false>(xbase, cnt, lane, w, p, sh_sc);
    }
    __syncthreads();

    // phase 2: chunk softmax per m (warp w handles m = w; 4 scores per lane)
    {
        float sc[4], e[4];
        #pragma unroll
        for (int i = 0; i < 4; i++) sc[i] = sh_sc[(lane + 32 * i) * 9 + w];
        float mx = fmaxf(fmaxf(sc[0], sc[1]), fmaxf(sc[2], sc[3]));
        mx = bflymax(mx);
        float es = 0.f;
        #pragma unroll
        for (int i = 0; i < 4; i++) {
            e[i] = (sc[i] == -INFINITY) ? 0.f : __expf(sc[i] - mx);
            es += e[i];
        }
        float den = bflysum(es);
        #pragma unroll
        for (int i = 0; i < 4; i++) sh_w[(lane + 32 * i) * Mq + w] = e[i];
        if (lane == 0) { g_smax[b][sp][w] = mx; g_sden[b][sp][w] = den; }
    }
    __syncthreads();

    // phase 3: pooling + weighted merge; re-read X from gmem (L2-hot)
    if (t < Dd / 4) {
        const int d0 = t * 4;
        float4 s4  = make_float4(0.f, 0.f, 0.f, 0.f);
        float4 mx4 = make_float4(-INFINITY, -INFINITY, -INFINITY, -INFINITY);
        float4 mn4 = make_float4( INFINITY,  INFINITY,  INFINITY,  INFINITY);
        float4 mg[Mq];
        #pragma unroll
        for (int m = 0; m < Mq; m++) mg[m] = make_float4(0.f, 0.f, 0.f, 0.f);

        #pragma unroll 8
        for (int s = 0; s < cnt; s++) {
            float4 x  = *(const float4*)(xbase + (size_t)s * Dd + d0);
            float4 w0 = *(const float4*)&sh_w[s * Mq];
            float4 w1 = *(const float4*)&sh_w[s * Mq + 4];
            s4.x += x.x; s4.y += x.y; s4.z += x.z; s4.w += x.w;
            mx4.x = fmaxf(mx4.x, x.x); mx4.y = fmaxf(mx4.y, x.y);
            mx4.z = fmaxf(mx4.z, x.z); mx4.w = fmaxf(mx4.w, x.w);
            mn4.x = fminf(mn4.x, x.x); mn4.y = fminf(mn4.y, x.y);
            mn4.z = fminf(mn4.z, x.z); mn4.w = fminf(mn4.w, x.w);
            float wm[Mq] = {w0.x, w0.y, w0.z, w0.w, w1.x, w1.y, w1.z, w1.w};
            #pragma unroll
            for (int m = 0; m < Mq; m++) {
                mg[m].x = fmaf(wm[m], x.x, mg[m].x);
                mg[m].y = fmaf(wm[m], x.y, mg[m].y);
                mg[m].z = fmaf(wm[m], x.z, mg[m].z);
                mg[m].w = fmaf(wm[m], x.w, mg[m].w);
            }
        }
        *(float4*)&g_psum[b][sp][d0] = s4;
        *(float4*)&g_pmax[b][sp][d0] = mx4;
        *(float4*)&g_pmin[b][sp][d0] = mn4;
        #pragma unroll
        for (int m = 0; m < Mq; m++)
            *(float4*)&g_pm[b][sp][m][d0] = mg[m];
    }
}

// ---------------- kernel 2: combine partials; grid (Bb, 11, 2), block 768 ----------------
// unit u: 0..7 = merged m; 8 = mean (+clf); 9 = max; 10 = min
// 8 split-groups x 96 col-threads; blockIdx.z selects column half; smem tree.
__global__ __launch_bounds__(768) void k_combine(
    const float* __restrict__ tokens, const int* __restrict__ lengths)
{
    const int b  = blockIdx.x;
    const int u  = blockIdx.y;
    const int cz = blockIdx.z;     // column half
    const int t  = threadIdx.x;
    const int g  = t / 96;         // split group (2 splits each), 0..7
    const int tt = t - g * 96;     // column thread within half
    const int d0 = (cz * 96 + tt) * 4;

    __shared__ int    shc[SPLITS];
    __shared__ float  shf[SPLITS];
    __shared__ float  shinv;
    __shared__ float4 red[8][96];

    if (t < SPLITS) {
        int c = g_cnt[b][t];
        shc[t] = c;
        if (u < Mq) {
            float sm = c > 0 ? g_smax[b][t][u] : -INFINITY;
            float sd = c > 0 ? g_sden[b][t][u] : 0.f;
            float gm = bflymax16(sm);
            float f  = c > 0 ? __expf(sm - gm) : 0.f;
            float gd = bflysum16(sd * f);
            shf[t] = f;
            if (t == 0) shinv = (gd > 0.f) ? (1.f / gd) : 0.f;
        }
    }
    __syncthreads();

    if (u < Mq) {
        float4 a = make_float4(0.f, 0.f, 0.f, 0.f);
        #pragma unroll
        for (int i = 0; i < 2; i++) {
            const int sp = g * 2 + i;
            float f = shf[sp];
            float4 v = *(const float4*)&g_pm[b][sp][u][d0];
            a.x = fmaf(f, v.x, a.x); a.y = fmaf(f, v.y, a.y);
            a.z = fmaf(f, v.z, a.z); a.w = fmaf(f, v.w, a.w);
        }
        red[g][tt] = a;
        __syncthreads();
        if (g == 0) {
            #pragma unroll
            for (int r = 1; r < 8; r++) {
                float4 v = red[r][tt];
                a.x += v.x; a.y += v.y; a.z += v.z; a.w += v.w;
            }
            float iv = shinv;
            *(float4*)&g_xb[b][u*Dd + d0] = make_float4(a.x*iv, a.y*iv, a.z*iv, a.w*iv);
        }
    } else if (u == Mq) {
        float4 s = make_float4(0.f, 0.f, 0.f, 0.f);
        #pragma unroll
        for (int i = 0; i < 2; i++) {
            const int sp = g * 2 + i;
            if (shc[sp] <= 0) continue;
            float4 v = *(const float4*)&g_psum[b][sp][d0];
            s.x += v.x; s.y += v.y; s.z += v.z; s.w += v.w;
        }
        red[g][tt] = s;
        __syncthreads();
        if (g == 0) {
            #pragma unroll
            for (int r = 1; r < 8; r++) {
                float4 v = red[r][tt];
                s.x += v.x; s.y += v.y; s.z += v.z; s.w += v.w;
            }
            float invlen = 1.f / (float)read_len(lengths, b);
            *(float4*)&g_xa[b][d0] = make_float4(s.x*invlen, s.y*invlen, s.z*invlen, s.w*invlen);
            *(float4*)&g_xb[b][Mq*Dd + d0] = *(const float4*)(tokens + (size_t)b * (Ss + 1) * Dd + d0);
        }
    } else if (u == Mq + 1) {
        float4 mx = make_float4(-INFINITY, -INFINITY, -INFINITY, -INFINITY);
        #pragma unroll
        for (int i = 0; i < 2; i++) {
            const int sp = g * 2 + i;
            if (shc[sp] <= 0) continue;
            float4 v = *(const float4*)&g_pmax[b][sp][d0];
            mx.x = fmaxf(mx.x, v.x); mx.y = fmaxf(mx.y, v.y);
            mx.z = fmaxf(mx.z, v.z); mx.w = fmaxf(mx.w, v.w);
        }
        red[g][tt] = mx;
        __syncthreads();
        if (g == 0) {
            #pragma unroll
            for (int r = 1; r < 8; r++) {
                float4 v = red[r][tt];
                mx.x = fmaxf(mx.x, v.x); mx.y = fmaxf(mx.y, v.y);
                mx.z = fmaxf(mx.z, v.z); mx.w = fmaxf(mx.w, v.w);
            }
            *(float4*)&g_xa[b][Dd + d0] = mx;
        }
    } else {
        float4 mn = make_float4(INFINITY, INFINITY, INFINITY, INFINITY);
        #pragma unroll
        for (int i = 0; i < 2; i++) {
            const int sp = g * 2 + i;
            if (shc[sp] <= 0) continue;
            float4 v = *(const float4*)&g_pmin[b][sp][d0];
            mn.x = fminf(mn.x, v.x); mn.y = fminf(mn.y, v.y);
            mn.z = fminf(mn.z, v.z); mn.w = fminf(mn.w, v.w);
        }
        red[g][tt] = mn;
        __syncthreads();
        if (g == 0) {
            #pragma unroll
            for (int r = 1; r < 8; r++) {
                float4 v = red[r][tt];
                mn.x = fminf(mn.x, v.x); mn.y = fminf(mn.y, v.y);
                mn.z = fminf(mn.z, v.z); mn.w = fminf(mn.w, v.w);
            }
            *(float4*)&g_xa[b][2*Dd + d0] = mn;
        }
    }
}

// ---------------- GEMM body (all 16 batch rows per CTA; W read once) ----------------
__device__ __forceinline__ void gemm_body16_atomic(
    const float* __restrict__ A, int lda, const float* __restrict__ W,
    float* __restrict__ H, int hstride, int hoff, int k0)
{
    __shared__ float sA[16 * KC];
    const int j = blockIdx.x * 256 + threadIdx.x;   // blockIdx.x in 0..2

    for (int i = threadIdx.x; i < 16 * KC; i += 256) {
        int bb = i / KC;
        int kk = i - bb * KC;
        sA[i] = A[bb * lda + k0 + kk];
    }
    __syncthreads();

    float acc[16];
    #pragma unroll
    for (int bb = 0; bb < 16; bb++) acc[bb] = 0.f;

    const float* Wp = W + (size_t)k0 * Dd + j;
    #pragma unroll
    for (int kk = 0; kk < KC; kk += 8) {
        float wv[8];
        #pragma unroll
        for (int u = 0; u < 8; u++) wv[u] = Wp[u * Dd];
        Wp += 8 * Dd;
        #pragma unroll
        for (int bb = 0; bb < 16; bb++) {
            float4 a0 = *(const float4*)&sA[bb * KC + kk];
            float4 a1 = *(const float4*)&sA[bb * KC + kk + 4];
            float v = acc[bb];
            v = fmaf(a0.x, wv[0], v);
            v = fmaf(a0.y, wv[1], v);
            v = fmaf(a0.z, wv[2], v);
            v = fmaf(a0.w, wv[3], v);
            v = fmaf(a1.x, wv[4], v);
            v = fmaf(a1.y, wv[5], v);
            v = fmaf(a1.z, wv[6], v);
            v = fmaf(a1.w, wv[7], v);
            acc[bb] = v;
        }
    }
    #pragma unroll
    for (int bb = 0; bb < 16; bb++)
        atomicAdd(&H[(size_t)bb * hstride + hoff + j], acc[bb]);
}

// layer-1 GEMM, both branches, atomic into g_h
__global__ __launch_bounds__(256) void k_g1(const float* __restrict__ w1a, const float* __restrict__ w1b)
{
    const int br = blockIdx.z;
    if (br == 0 && blockIdx.y >= NS_A) return;
    const float* A = br ? &g_xb[0][0] : &g_xa[0][0];
    const int lda  = br ? (Mq + 1) * Dd : 3 * Dd;
    const float* W = br ? w1b : w1a;
    float* H = br ? g_hB : g_hA;
    gemm_body16_atomic(A, lda, W, H, Dd, 0, blockIdx.y * KC);
}

// activation: h = gelu(h + b1), both branches
__global__ __launch_bounds__(256) void k_act(const float* __restrict__ b1a, const float* __restrict__ b1b)
{
    const int br  = blockIdx.y;
    const int idx = blockIdx.x * 256 + threadIdx.x;   // 0..12287
    const int j   = idx % Dd;
    float* H = br ? g_hB : g_hA;
    float v = H[idx] + (br ? b1b[j] : b1a[j]);
    H[idx] = 0.5f * v * (1.f + erff(v * 0.70710678118654752f));
}

// layer-2 GEMM, both branches, atomic into out (pre-initialized with bias)
__global__ __launch_bounds__(256) void k_g2(const float* __restrict__ w2a, const float* __restrict__ w2b,
                                            float* __restrict__ out)
{
    const int br = blockIdx.z;
    const float* A = br ? g_hB : g_hA;
    const float* W = br ? w2b : w2a;
    gemm_body16_atomic(A, Dd, W, out, 2 * Dd, br * Dd, blockIdx.y * KC);
}

// ---------------- launch ----------------
extern "C" void kernel_launch(void* const* d_in, const int* in_sizes, int n_in,
                              void* d_out, int out_size)
{
    const float* tokens  = (const float*)d_in[0];
    const int*   lengths = (const int*)d_in[1];
    const float* q       = (const float*)d_in[2];
    const float* lns     = (const float*)d_in[3];
    const float* lnb     = (const float*)d_in[4];
    const float* w1a     = (const float*)d_in[5];
    const float* b1a     = (const float*)d_in[6];
    const float* w2a     = (const float*)d_in[7];
    const float* b2a     = (const float*)d_in[8];
    const float* w1b     = (const float*)d_in[9];
    const float* b1b     = (const float*)d_in[10];
    const float* w2b     = (const float*)d_in[11];
    const float* b2b     = (const float*)d_in[12];
    float* out = (float*)d_out;

    k_prep<<<1, 256>>>(q, lns, lnb);
    k_init<<<96, 256>>>(b2a, b2b, out);
    k_main<<<Bb * SPLITS, 256>>>(tokens, lengths);
    k_combine<<<dim3(Bb, 11, 2), 768>>>(tokens, lengths);

    k_g1<<<dim3(3, NS_B, 2), 256>>>(w1a, w1b);
    k_act<<<dim3(48, 2), 256>>>(b1a, b1b);
    k_g2<<<dim3(3, NS_2, 2), 256>>>(w2a, w2b, out);
}